// round 5
// baseline (speedup 1.0000x reference)
#include <cuda_runtime.h>
#include <math.h>

#define NN 16800
#define KK 1024
#define BB 64
#define NT 1024
#define HP 257
#define NV 4200   // NN / 4

// ---- device-global scratch (allocation-free workaround) ----
__device__ float4             g_box [BB * KK];
__device__ float              g_area[BB * KK];
__device__ float              g_val [BB * KK];
__device__ float              g_kpt [BB * KK * 10];
__device__ unsigned long long g_mask[(size_t)BB * KK * 16];

// ================= Kernel 1: exact radix top-K select + sort + decode =================
struct S1 {
    unsigned okey[NN];              // 67200 B (16-aligned)
    unsigned hist32[32 * HP];       // 32896 B
    unsigned long long cand[KK];    // 8192 B
    unsigned warpsum[8];
    unsigned pref_arr[5];
    int kr_arr[5];
    int wsum[32];
    int cntgt;
    int eqtot;
};

__global__ __launch_bounds__(NT, 1)
void k_select(const float* __restrict__ p_loc,
              const float* __restrict__ p_conf,
              const float* __restrict__ p_landms,
              const float* __restrict__ anchors)
{
    extern __shared__ char raw[];
    S1* s = reinterpret_cast<S1*>(raw);
    const int b = blockIdx.x, tid = threadIdx.x;
    const int lane = tid & 31, wrp = tid >> 5;
    const float* conf = p_conf + (size_t)b * NN;
    const float4* conf4 = (const float4*)conf;
    uint4* ok4p = (uint4*)s->okey;

    if (tid == 0) { s->pref_arr[0] = 0u; s->kr_arr[0] = KK; s->cntgt = 0; s->eqtot = 0; }

    // ================= 4 radix passes (8 bits), vectorized x4 =================
    #pragma unroll
    for (int p = 0; p < 4; p++) {
        const int shift = 24 - 8 * p;
        {   // zero per-warp hist (16B vector)
            uint4 z = make_uint4(0u, 0u, 0u, 0u);
            uint4* h4 = (uint4*)s->hist32;
            for (int t = tid; t < (32 * HP) / 4; t += NT) h4[t] = z;
        }
        __syncthreads();
        const unsigned prefv = s->pref_arr[p];
        const int krloc = s->kr_arr[p];

        for (int it = 0; it < 5; it++) {
            int vb = it * NT + tid;
            bool valid = (vb < NV);
            uint4 ok4 = make_uint4(0u, 0u, 0u, 0u);
            if (p == 0) {
                if (valid) {
                    float4 c4 = conf4[vb];
                    ok4.x = (c4.x >= 0.0f) ? (__float_as_uint(c4.x) | 0x80000000u) : 0u;
                    ok4.y = (c4.y >= 0.0f) ? (__float_as_uint(c4.y) | 0x80000000u) : 0u;
                    ok4.z = (c4.z >= 0.0f) ? (__float_as_uint(c4.z) | 0x80000000u) : 0u;
                    ok4.w = (c4.w >= 0.0f) ? (__float_as_uint(c4.w) | 0x80000000u) : 0u;
                    ok4p[vb] = ok4;
                }
            } else {
                if (valid) ok4 = ok4p[vb];
            }
            unsigned oks[4] = {ok4.x, ok4.y, ok4.z, ok4.w};
            #pragma unroll
            for (int e = 0; e < 4; e++) {
                unsigned ok = oks[e];
                bool part;
                if (p == 0) part = valid;
                else        part = valid && ((ok >> (shift + 8)) == prefv);
                unsigned bucket = part ? ((ok >> shift) & 255u) : 0xFFFFFFFFu;
                unsigned grp = __match_any_sync(0xffffffffu, bucket);
                if (part && lane == (__ffs(grp) - 1))
                    s->hist32[wrp * HP + bucket] += (unsigned)__popc(grp);
            }
        }
        __syncthreads();

        // parallel digit find (threads 0..255 own buckets, suffix-scan)
        unsigned cnt = 0, ssum = 0;
        if (tid < 256) {
            #pragma unroll
            for (int w = 0; w < 32; w++) cnt += s->hist32[w * HP + tid];
            ssum = cnt;
            #pragma unroll
            for (int d = 1; d < 32; d <<= 1) {
                unsigned x = __shfl_down_sync(0xffffffffu, ssum, d);
                if (lane + d < 32) ssum += x;
            }
            if (lane == 0) s->warpsum[wrp] = ssum;
        }
        __syncthreads();
        if (tid < 256) {
            unsigned hi = 0;
            for (int w = wrp + 1; w < 8; w++) hi += s->warpsum[w];
            unsigned S = ssum + hi;
            if (S >= (unsigned)krloc && S - cnt < (unsigned)krloc) {
                s->pref_arr[p + 1] = (prefv << 8) | (unsigned)tid;
                s->kr_arr[p + 1] = krloc - (int)(S - cnt);
                s->eqtot = (int)cnt;
            }
        }
        __syncthreads();
    }

    const unsigned T = s->pref_arr[4];
    const int need = s->kr_arr[4];
    const int eq0 = KK - need;
    const bool fastpath = (s->eqtot == need) && (T != 0u);

    // ================= compaction =================
    if (fastpath) {
        int mycnt = 0;
        for (int it = 0; it < 5; it++) {
            int vb = it * NT + tid;
            bool valid = (vb < NV);
            uint4 ok4 = valid ? ok4p[vb] : make_uint4(0u, 0u, 0u, 0u);
            unsigned oks[4] = {ok4.x, ok4.y, ok4.z, ok4.w};
            #pragma unroll
            for (int e = 0; e < 4; e++)
                mycnt += __popc(__ballot_sync(0xffffffffu, valid && (oks[e] >= T)));
        }
        int wb = 0;
        if (lane == 0) wb = atomicAdd(&s->cntgt, mycnt);
        wb = __shfl_sync(0xffffffffu, wb, 0);
        for (int it = 0; it < 5; it++) {
            int vb = it * NT + tid;
            bool valid = (vb < NV);
            uint4 ok4 = valid ? ok4p[vb] : make_uint4(0u, 0u, 0u, 0u);
            unsigned oks[4] = {ok4.x, ok4.y, ok4.z, ok4.w};
            #pragma unroll
            for (int e = 0; e < 4; e++) {
                bool take = valid && (oks[e] >= T);
                unsigned bal = __ballot_sync(0xffffffffu, take);
                if (take) {
                    int pos = wb + __popc(bal & ((1u << lane) - 1u));
                    int i = vb * 4 + e;
                    s->cand[pos] = (((unsigned long long)oks[e]) << 32) | (unsigned)(~(unsigned)i);
                }
                wb += __popc(bal);
            }
        }
        __syncthreads();
    } else {
        int eqbase = 0;
        for (int base = 0; base < NN; base += NT) {
            int i = base + tid;
            bool v = (i < NN);
            unsigned ok = v ? s->okey[i] : 0u;
            bool gt = v && (ok > T);
            bool eq = v && (ok == T);
            if (gt) {
                int p2 = atomicAdd(&s->cntgt, 1);
                s->cand[p2] = (((unsigned long long)ok) << 32) | (unsigned)(~(unsigned)i);
            }
            unsigned bal = __ballot_sync(0xffffffffu, eq);
            if (lane == 0) s->wsum[wrp] = __popc(bal);
            __syncthreads();
            int woff = 0, tot = 0;
            #pragma unroll
            for (int w = 0; w < 32; w++) { int x = s->wsum[w]; if (w < wrp) woff += x; tot += x; }
            int rank = eqbase + woff + __popc(bal & ((1u << lane) - 1u));
            if (eq && rank < need)
                s->cand[eq0 + rank] = (((unsigned long long)T) << 32) | (unsigned)(~(unsigned)i);
            eqbase += tot;
            __syncthreads();
        }
    }

    // ================= bitonic sort descending; warp-local shfl phases for j<=16 =================
    {   // k2 = 2..32 fully warp-local
        unsigned long long v = s->cand[tid];
        #pragma unroll
        for (int k2 = 2; k2 <= 32; k2 <<= 1) {
            #pragma unroll
            for (int j = k2 >> 1; j >= 1; j >>= 1) {
                unsigned long long pv = __shfl_xor_sync(0xffffffffu, v, j);
                bool keepMax = ((tid & k2) == 0) == ((tid & j) == 0);
                v = keepMax ? (v > pv ? v : pv) : (v < pv ? v : pv);
            }
        }
        s->cand[tid] = v;
    }
    __syncthreads();
    for (int k2 = 64; k2 <= KK; k2 <<= 1) {
        for (int j = k2 >> 1; j >= 32; j >>= 1) {
            int ixj = tid ^ j;
            if (ixj > tid) {
                unsigned long long a = s->cand[tid], cc = s->cand[ixj];
                bool sw = ((tid & k2) == 0) ? (a < cc) : (a > cc);
                if (sw) { s->cand[tid] = cc; s->cand[ixj] = a; }
            }
            __syncthreads();
        }
        unsigned long long v = s->cand[tid];
        #pragma unroll
        for (int j = 16; j >= 1; j >>= 1) {
            unsigned long long pv = __shfl_xor_sync(0xffffffffu, v, j);
            bool keepMax = ((tid & k2) == 0) == ((tid & j) == 0);
            v = keepMax ? (v > pv ? v : pv) : (v < pv ? v : pv);
        }
        s->cand[tid] = v;
        __syncthreads();
    }

    // ================= gather + decode 1024 rows -> global scratch =================
    {
        int t = tid;
        unsigned long long cd = s->cand[t];
        int idx = (int)(~(unsigned)cd);
        unsigned ok = (unsigned)(cd >> 32);
        float c = __uint_as_float(ok & 0x7FFFFFFFu);
        float val = (ok != 0u) ? (1.0f / (1.0f + expf(-c))) : -1.0f;
        float4 a = ((const float4*)anchors)[idx];
        float4 l = ((const float4*)p_loc)[(size_t)b * NN + idx];
        float cx = a.x + l.x * 0.1f * a.z;
        float cy = a.y + l.y * 0.1f * a.w;
        float w = a.z * expf(l.z * 0.2f);
        float h = a.w * expf(l.w * 0.2f);
        float x1 = cx - w * 0.5f, y1 = cy - h * 0.5f;
        float x2 = cx + w * 0.5f, y2 = cy + h * 0.5f;
        g_box[b * KK + t] = make_float4(x1, y1, x2, y2);
        g_area[b * KK + t] = fmaxf(x2 - x1, 0.0f) * fmaxf(y2 - y1, 0.0f);
        g_val[b * KK + t] = val;
        const float* lm = p_landms + ((size_t)b * NN + idx) * 10;
        #pragma unroll
        for (int p2 = 0; p2 < 5; p2++) {
            g_kpt[(b * KK + t) * 10 + 2 * p2]     = a.x + lm[2 * p2]     * 0.1f * a.z;
            g_kpt[(b * KK + t) * 10 + 2 * p2 + 1] = a.y + lm[2 * p2 + 1] * 0.1f * a.w;
        }
    }
}

// ================= Kernel 2: full suppression bitmask, full-chip =================
__global__ __launch_bounds__(256)
void k_mask()
{
    __shared__ float4 cb[64];
    __shared__ float  ca[64];
    const int w = blockIdx.x;     // word group 0..15
    const int b = blockIdx.y;     // image
    const int tid = threadIdx.x;
    const float4* box = g_box + b * KK;
    const float*  area = g_area + b * KK;

    if (tid < 64) { cb[tid] = box[w * 64 + tid]; ca[tid] = area[w * 64 + tid]; }
    __syncthreads();

    const int imax = (w + 1) * 64;   // rows i >= imax never read word w
    for (int i = tid; i < imax; i += 256) {
        unsigned long long m = 0ull;
        int j0 = (w * 64 > i + 1) ? (w * 64) : (i + 1);
        int l0 = j0 - w * 64;
        float4 bi = box[i];
        float ai = area[i];
        for (int l = l0; l < 64; l++) {
            float4 bj = cb[l];
            float lx = fmaxf(bi.x, bj.x);
            float ly = fmaxf(bi.y, bj.y);
            float rx = fminf(bi.z, bj.z);
            float ry = fminf(bi.w, bj.w);
            float ww = fmaxf(rx - lx, 0.0f);
            float hh = fmaxf(ry - ly, 0.0f);
            if (ww > 0.0f && hh > 0.0f) {          // inter==0 -> iou==0, never > 0.3
                float inter = ww * hh;
                float iou = __fdiv_rn(inter, ai + ca[l] - inter + 1e-9f);
                if (iou > 0.3f) m |= (1ull << l);
            }
        }
        g_mask[((size_t)(b * KK + i)) * 16 + w] = m;
    }
}

// ================= Kernel 3: blocked greedy scan + masked output =================
struct S3 {
    unsigned long long smask[KK * 17];   // row-padded (17) to break bank conflicts
    float sval[KK];
    unsigned long long acc[16];          // suppression carried into future chunks
    unsigned long long skept[16];
    unsigned sconf[32];
};

__global__ __launch_bounds__(NT, 1)
void k_scan(float* __restrict__ out)
{
    extern __shared__ char raw[];
    S3* s = reinterpret_cast<S3*>(raw);
    const int b = blockIdx.x, tid = threadIdx.x;
    const int lane = tid & 31, wrp = tid >> 5;

    // stage masks (padded) + vals + conf-alive ballots
    const unsigned long long* gm = g_mask + (size_t)b * KK * 16;
    for (int t = tid; t < KK * 16; t += NT)
        s->smask[(t >> 4) * 17 + (t & 15)] = gm[t];
    float v = g_val[b * KK + tid];
    s->sval[tid] = v;
    unsigned bal = __ballot_sync(0xffffffffu, v >= 0.5f);
    if (lane == 0) s->sconf[wrp] = bal;
    if (tid < 16) s->acc[tid] = 0ull;
    __syncthreads();

    #pragma unroll 1
    for (int c = 0; c < 16; c++) {
        if (tid < 32) {   // warp 0: ffs-skip scan over chunk c
            unsigned long long confw = (unsigned long long)s->sconf[2 * c]
                                     | ((unsigned long long)s->sconf[2 * c + 1] << 32);
            unsigned long long a = confw & ~s->acc[c];
            unsigned long long dlo = s->smask[(c * 64 + lane) * 17 + c];
            unsigned long long dhi = s->smask[(c * 64 + 32 + lane) * 17 + c];
            unsigned long long kept = 0ull;
            while (a) {
                int t = __ffsll((long long)a) - 1;
                unsigned long long bit = 1ull << t;
                kept |= bit;
                unsigned long long mrow = (t < 32)
                    ? __shfl_sync(0xffffffffu, dlo, t)
                    : __shfl_sync(0xffffffffu, dhi, t - 32);
                a &= ~(mrow | bit);
            }
            if (lane == 0) s->skept[c] = kept;
        }
        __syncthreads();
        // apply: warp w (1..15) ORs kept rows' word w into acc[w]
        if (wrp >= 1 && wrp < 16 && wrp > c) {
            unsigned long long kept = s->skept[c];
            unsigned long long m = 0ull;
            if ((kept >> lane) & 1ull)        m  = s->smask[(c * 64 + lane) * 17 + wrp];
            if ((kept >> (lane + 32)) & 1ull) m |= s->smask[(c * 64 + 32 + lane) * 17 + wrp];
            #pragma unroll
            for (int d = 16; d >= 1; d >>= 1)
                m |= __shfl_xor_sync(0xffffffffu, m, d);
            if (lane == 0) s->acc[wrp] |= m;
        }
        __syncthreads();
    }

    // masked output: [ltrb(4) | kpts(10) | score(1)] * keep
    const float* kpt = g_kpt + (size_t)b * KK * 10;
    float* outp = out + (size_t)b * KK * 15;
    for (int e = tid; e < KK * 15; e += NT) {
        int r = e / 15;
        int c2 = e - r * 15;
        float m = ((s->skept[r >> 6] >> (r & 63)) & 1ull) ? 1.0f : 0.0f;
        float vv;
        if (c2 < 4)       vv = ((const float*)&g_box[b * KK + r])[c2];
        else if (c2 < 14) vv = kpt[r * 10 + (c2 - 4)];
        else              vv = s->sval[r];
        outp[e] = vv * m;
    }
}

extern "C" void kernel_launch(void* const* d_in, const int* in_sizes, int n_in,
                              void* d_out, int out_size) {
    const float* p_loc    = (const float*)d_in[0];
    const float* p_conf   = (const float*)d_in[1];
    const float* p_landms = (const float*)d_in[2];
    const float* anchors  = (const float*)d_in[3];

    cudaFuncSetAttribute(k_select, cudaFuncAttributeMaxDynamicSharedMemorySize, (int)sizeof(S1));
    cudaFuncSetAttribute(k_scan,   cudaFuncAttributeMaxDynamicSharedMemorySize, (int)sizeof(S3));

    k_select<<<BB, NT, sizeof(S1)>>>(p_loc, p_conf, p_landms, anchors);
    k_mask<<<dim3(16, BB), 256>>>();
    k_scan<<<BB, NT, sizeof(S3)>>>((float*)d_out);
}

// round 7
// speedup vs baseline: 1.6382x; 1.6382x over previous
#include <cuda_runtime.h>
#include <math.h>

#define NN 16800
#define KK 1024
#define BB 64
#define NT 1024
#define HP 257
#define SVMAX 6144

struct SF {
    union {
        struct {                              // select phase
            unsigned okey[NN];                // 67200 B
            unsigned hist32[32 * HP];         // 32896 B
            unsigned long long surv[SVMAX];   // 49152 B
            unsigned hist256[256];            // 1024 B
        } a;
        struct {                              // nms phase
            float4 sbox[KK];
            float  sarea[KK];
            float  sval[KK];
            float  smult[KK];
            unsigned long long smask[KK];
            float  skpt[KK * 10];
        } n;
    } u;
    unsigned long long cand[KK];
    unsigned long long s_kept;
    unsigned warpsum[8];
    unsigned pref_arr[5];
    int kr_arr[5];
    int wsum[32];
    int cntgt;
    int svcnt;
    int eqtot;
};

// exact-equivalent IoU>0.3 test (bit-identical decisions to __fdiv_rn(...)>0.3f)
__device__ __forceinline__ bool iou_gt(float inter, float den) {
    if (inter > 0.301f * den) return true;
    if (inter > 0.299f * den) return __fdiv_rn(inter, den) > 0.3f;
    return false;
}

__global__ __launch_bounds__(NT, 1)
void k_fused(const float* __restrict__ p_loc,
             const float* __restrict__ p_conf,
             const float* __restrict__ p_landms,
             const float* __restrict__ anchors,
             float* __restrict__ out)
{
    extern __shared__ char raw[];
    SF* s = reinterpret_cast<SF*>(raw);
    const int b = blockIdx.x, tid = threadIdx.x;
    const int lane = tid & 31, wrp = tid >> 5;
    const float* conf = p_conf + (size_t)b * NN;

    if (tid == 0) { s->pref_arr[0] = 0u; s->kr_arr[0] = KK; s->cntgt = 0; s->svcnt = 0; s->eqtot = 0; }

    // ================= pass 0: 8-bit top byte, per-warp histograms =================
    for (int t = tid; t < 32 * HP; t += NT) s->u.a.hist32[t] = 0u;
    __syncthreads();
    for (int base = 0; base < NN; base += NT) {
        int i = base + tid;
        bool v = (i < NN);
        unsigned ok = 0u;
        if (v) {
            float c = conf[i];
            ok = (c >= 0.0f) ? (__float_as_uint(c) | 0x80000000u) : 0u;
            s->u.a.okey[i] = ok;
        }
        unsigned bucket = v ? (ok >> 24) : 0xFFFFFFFFu;
        unsigned grp = __match_any_sync(0xffffffffu, bucket);
        if (v && lane == (__ffs(grp) - 1))
            s->u.a.hist32[wrp * HP + bucket] += (unsigned)__popc(grp);
    }
    __syncthreads();
    {   // digit find (threads 0..255 own buckets)
        unsigned cnt = 0, ssum = 0;
        if (tid < 256) {
            #pragma unroll
            for (int w = 0; w < 32; w++) cnt += s->u.a.hist32[w * HP + tid];
            ssum = cnt;
            #pragma unroll
            for (int d = 1; d < 32; d <<= 1) {
                unsigned x = __shfl_down_sync(0xffffffffu, ssum, d);
                if (lane + d < 32) ssum += x;
            }
            if (lane == 0) s->warpsum[wrp] = ssum;
        }
        __syncthreads();
        if (tid < 256) {
            unsigned hi = 0;
            for (int w = wrp + 1; w < 8; w++) hi += s->warpsum[w];
            unsigned S = ssum + hi;
            if (S >= (unsigned)KK && S - cnt < (unsigned)KK) {
                s->pref_arr[1] = (unsigned)tid;
                s->kr_arr[1] = KK - (int)(S - cnt);
                s->eqtot = (int)cnt;
            }
        }
        __syncthreads();
    }

    const int E0 = s->eqtot;
    const unsigned d0 = s->pref_arr[1];
    bool compacted = false;

    if (E0 <= SVMAX) {
        // ============ compact: top byte > d0 -> cand (order-free); == d0 -> surv ============
        for (int base = 0; base < NN; base += NT) {
            int i = base + tid;
            bool v = (i < NN);
            unsigned ok = v ? s->u.a.okey[i] : 0u;
            bool gt = v && ((ok >> 24) > d0);
            bool eq = v && ((ok >> 24) == d0);
            unsigned balg = __ballot_sync(0xffffffffu, gt);
            int pg = 0;
            if (lane == 0 && balg) pg = atomicAdd(&s->cntgt, __popc(balg));
            pg = __shfl_sync(0xffffffffu, pg, 0);
            if (gt) s->cand[pg + __popc(balg & ((1u << lane) - 1u))] =
                        (((unsigned long long)ok) << 32) | (unsigned)(~(unsigned)i);
            unsigned bale = __ballot_sync(0xffffffffu, eq);
            int pe = 0;
            if (lane == 0 && bale) pe = atomicAdd(&s->svcnt, __popc(bale));
            pe = __shfl_sync(0xffffffffu, pe, 0);
            if (eq) s->u.a.surv[pe + __popc(bale & ((1u << lane) - 1u))] =
                        (((unsigned long long)ok) << 32) | (unsigned)(~(unsigned)i);
        }
        __syncthreads();
        const int svn = s->svcnt;
        const int iters = (svn + NT - 1) / NT;

        // ============ passes 1..3 over survivors (shared 256-bucket hist) ============
        for (int p = 1; p < 4; p++) {
            const int shift = 24 - 8 * p;
            if (tid < 256) s->u.a.hist256[tid] = 0u;
            __syncthreads();
            const unsigned prefv = s->pref_arr[p];
            const int krloc = s->kr_arr[p];
            for (int it = 0; it < iters; it++) {
                int ix = it * NT + tid;
                bool valid = (ix < svn);
                unsigned key = valid ? (unsigned)(s->u.a.surv[ix] >> 32) : 0u;
                bool part = valid && ((key >> (shift + 8)) == prefv);
                unsigned bucket = part ? ((key >> shift) & 255u) : 0xFFFFFFFFu;
                unsigned grp = __match_any_sync(0xffffffffu, bucket);
                if (part && lane == (__ffs(grp) - 1))
                    atomicAdd(&s->u.a.hist256[bucket], (unsigned)__popc(grp));
            }
            __syncthreads();
            unsigned cnt = 0, ssum = 0;
            if (tid < 256) {
                cnt = s->u.a.hist256[tid];
                ssum = cnt;
                #pragma unroll
                for (int d = 1; d < 32; d <<= 1) {
                    unsigned x = __shfl_down_sync(0xffffffffu, ssum, d);
                    if (lane + d < 32) ssum += x;
                }
                if (lane == 0) s->warpsum[wrp] = ssum;
            }
            __syncthreads();
            if (tid < 256) {
                unsigned hi = 0;
                for (int w = wrp + 1; w < 8; w++) hi += s->warpsum[w];
                unsigned S = ssum + hi;
                if (S >= (unsigned)krloc && S - cnt < (unsigned)krloc) {
                    s->pref_arr[p + 1] = (prefv << 8) | (unsigned)tid;
                    s->kr_arr[p + 1] = krloc - (int)(S - cnt);
                    s->eqtot = (int)cnt;
                }
            }
            __syncthreads();
        }

        // ============ fast final compaction over survivors ============
        if (s->eqtot == s->kr_arr[4]) {
            const unsigned T = s->pref_arr[4];
            for (int it = 0; it < iters; it++) {
                int ix = it * NT + tid;
                bool valid = (ix < svn);
                unsigned long long sv = valid ? s->u.a.surv[ix] : 0ull;
                bool take = valid && ((unsigned)(sv >> 32) >= T);
                unsigned bal = __ballot_sync(0xffffffffu, take);
                int pg = 0;
                if (lane == 0 && bal) pg = atomicAdd(&s->cntgt, __popc(bal));
                pg = __shfl_sync(0xffffffffu, pg, 0);
                if (take) s->cand[pg + __popc(bal & ((1u << lane) - 1u))] = sv;
            }
            compacted = true;
            __syncthreads();
        }
    } else {
        // ============ full-scan passes 1..3 (per-warp hist) ============
        for (int p = 1; p < 4; p++) {
            const int shift = 24 - 8 * p;
            for (int t = tid; t < 32 * HP; t += NT) s->u.a.hist32[t] = 0u;
            __syncthreads();
            const unsigned prefv = s->pref_arr[p];
            const int krloc = s->kr_arr[p];
            for (int base = 0; base < NN; base += NT) {
                int i = base + tid;
                bool v = (i < NN);
                unsigned ok = v ? s->u.a.okey[i] : 0u;
                bool part = v && ((ok >> (shift + 8)) == prefv);
                unsigned bucket = part ? ((ok >> shift) & 255u) : 0xFFFFFFFFu;
                unsigned grp = __match_any_sync(0xffffffffu, bucket);
                if (part && lane == (__ffs(grp) - 1))
                    s->u.a.hist32[wrp * HP + bucket] += (unsigned)__popc(grp);
            }
            __syncthreads();
            unsigned cnt = 0, ssum = 0;
            if (tid < 256) {
                #pragma unroll
                for (int w = 0; w < 32; w++) cnt += s->u.a.hist32[w * HP + tid];
                ssum = cnt;
                #pragma unroll
                for (int d = 1; d < 32; d <<= 1) {
                    unsigned x = __shfl_down_sync(0xffffffffu, ssum, d);
                    if (lane + d < 32) ssum += x;
                }
                if (lane == 0) s->warpsum[wrp] = ssum;
            }
            __syncthreads();
            if (tid < 256) {
                unsigned hi = 0;
                for (int w = wrp + 1; w < 8; w++) hi += s->warpsum[w];
                unsigned S = ssum + hi;
                if (S >= (unsigned)krloc && S - cnt < (unsigned)krloc) {
                    s->pref_arr[p + 1] = (prefv << 8) | (unsigned)tid;
                    s->kr_arr[p + 1] = krloc - (int)(S - cnt);
                    s->eqtot = (int)cnt;
                }
            }
            __syncthreads();
        }
        if (s->eqtot == s->kr_arr[4] && s->pref_arr[4] != 0u) {
            const unsigned T = s->pref_arr[4];
            if (tid == 0) s->cntgt = 0;
            __syncthreads();
            int mycnt = 0;
            for (int base = 0; base < NN; base += NT) {
                int i = base + tid;
                bool take = (i < NN) && (s->u.a.okey[i] >= T);
                mycnt += __popc(__ballot_sync(0xffffffffu, take));
            }
            int wb = 0;
            if (lane == 0) wb = atomicAdd(&s->cntgt, mycnt);
            wb = __shfl_sync(0xffffffffu, wb, 0);
            for (int base = 0; base < NN; base += NT) {
                int i = base + tid;
                bool take = (i < NN) && (s->u.a.okey[i] >= T);
                unsigned bal = __ballot_sync(0xffffffffu, take);
                if (take) {
                    int pos = wb + __popc(bal & ((1u << lane) - 1u));
                    s->cand[pos] = (((unsigned long long)s->u.a.okey[i]) << 32) | (unsigned)(~(unsigned)i);
                }
                wb += __popc(bal);
            }
            compacted = true;
            __syncthreads();
        }
    }

    // ============ stable fallback (rare: ties beyond cutoff or T==0) ============
    if (!compacted) {
        const unsigned T = s->pref_arr[4];
        const int need = s->kr_arr[4];
        const int eq0 = KK - need;
        __syncthreads();
        if (tid == 0) s->cntgt = 0;
        __syncthreads();
        int eqbase = 0;
        for (int base = 0; base < NN; base += NT) {
            int i = base + tid;
            bool v = (i < NN);
            unsigned ok = v ? s->u.a.okey[i] : 0u;
            bool gt = v && (ok > T);
            bool eq = v && (ok == T);
            if (gt) {
                int p2 = atomicAdd(&s->cntgt, 1);
                s->cand[p2] = (((unsigned long long)ok) << 32) | (unsigned)(~(unsigned)i);
            }
            unsigned bal = __ballot_sync(0xffffffffu, eq);
            if (lane == 0) s->wsum[wrp] = __popc(bal);
            __syncthreads();
            int woff = 0, tot = 0;
            #pragma unroll
            for (int w = 0; w < 32; w++) { int x = s->wsum[w]; if (w < wrp) woff += x; tot += x; }
            int rank = eqbase + woff + __popc(bal & ((1u << lane) - 1u));
            if (eq && rank < need)
                s->cand[eq0 + rank] = (((unsigned long long)T) << 32) | (unsigned)(~(unsigned)i);
            eqbase += tot;
            __syncthreads();
        }
    }

    // ================= bitonic sort descending (distinct 64-bit keys) =================
    for (int k2 = 2; k2 <= KK; k2 <<= 1) {
        for (int j = k2 >> 1; j > 0; j >>= 1) {
            int t = tid, ixj = t ^ j;
            if (ixj > t) {
                unsigned long long a = s->cand[t], c = s->cand[ixj];
                bool sw = ((t & k2) == 0) ? (a < c) : (a > c);
                if (sw) { s->cand[t] = c; s->cand[ixj] = a; }
            }
            __syncthreads();
        }
    }
    __syncthreads();   // select scratch (union .a) dead after this point

    // ================= gather + decode into smem (union .n) =================
    float4 bj; float aj; float vj;
    {
        int t = tid;
        unsigned long long cd = s->cand[t];
        int idx = (int)(~(unsigned)cd);
        unsigned ok = (unsigned)(cd >> 32);
        float c = __uint_as_float(ok & 0x7FFFFFFFu);
        vj = (ok != 0u) ? (1.0f / (1.0f + expf(-c))) : -1.0f;
        float4 a = ((const float4*)anchors)[idx];
        float4 l = ((const float4*)p_loc)[(size_t)b * NN + idx];
        float cx = a.x + l.x * 0.1f * a.z;
        float cy = a.y + l.y * 0.1f * a.w;
        float w = a.z * expf(l.z * 0.2f);
        float h = a.w * expf(l.w * 0.2f);
        float x1 = cx - w * 0.5f, y1 = cy - h * 0.5f;
        float x2 = cx + w * 0.5f, y2 = cy + h * 0.5f;
        bj = make_float4(x1, y1, x2, y2);
        aj = fmaxf(x2 - x1, 0.0f) * fmaxf(y2 - y1, 0.0f);
        s->u.n.sbox[t] = bj;
        s->u.n.sarea[t] = aj;
        s->u.n.sval[t] = vj;
        s->u.n.smult[t] = (ok != 0u) ? 1.0f : 0.0f;
        const float* lm = p_landms + ((size_t)b * NN + idx) * 10;
        #pragma unroll
        for (int p2 = 0; p2 < 5; p2++) {
            s->u.n.skpt[t * 10 + 2 * p2]     = a.x + lm[2 * p2]     * 0.1f * a.z;
            s->u.n.skpt[t * 10 + 2 * p2 + 1] = a.y + lm[2 * p2 + 1] * 0.1f * a.w;
        }
    }
    __syncthreads();

    // ================= Phase A: intra-chunk 64x64 suppression masks =================
    {
        int t64 = tid & 63, base = tid & ~63;
        unsigned long long m = 0ull;
        for (int j = t64 + 1; j < 64; j++) {
            float4 bq = s->u.n.sbox[base + j];
            float  aq = s->u.n.sarea[base + j];
            float lx = fmaxf(bj.x, bq.x);
            float ly = fmaxf(bj.y, bq.y);
            float rx = fminf(bj.z, bq.z);
            float ry = fminf(bj.w, bq.w);
            float ww = fmaxf(rx - lx, 0.0f);
            float hh = fmaxf(ry - ly, 0.0f);
            if (ww > 0.0f && hh > 0.0f) {
                float inter = ww * hh;
                float den = aj + aq - inter + 1e-9f;
                if (iou_gt(inter, den)) m |= (1ull << j);
            }
        }
        s->u.n.smask[tid] = m;
    }
    __syncthreads();

    // ================= Phase B: 16 sequential chunks =================
    #pragma unroll 1
    for (int c = 0; c < 16; c++) {
        if (tid < 32) {   // warp 0: ffs-skip scan (steps only on kept rows)
            int r0 = c * 64 + tid, r1 = r0 + 32;
            unsigned blo = __ballot_sync(0xffffffffu, s->u.n.smult[r0] != 0.0f);
            unsigned bhi = __ballot_sync(0xffffffffu, s->u.n.smult[r1] != 0.0f);
            unsigned long long a = (unsigned long long)blo | ((unsigned long long)bhi << 32);
            unsigned long long mlo = s->u.n.smask[r0];
            unsigned long long mhi = s->u.n.smask[r1];
            unsigned long long kept = 0ull;
            while (a) {
                int t = __ffsll((long long)a) - 1;
                kept |= (1ull << t);
                unsigned long long mrow = (t < 32)
                    ? __shfl_sync(0xffffffffu, mlo, t)
                    : __shfl_sync(0xffffffffu, mhi, t - 32);
                a &= ~(mrow | (1ull << t));
            }
            s->u.n.smult[r0] = ((kept >> tid) & 1ull) ? 1.0f : 0.0f;
            s->u.n.smult[r1] = ((kept >> (tid + 32)) & 1ull) ? 1.0f : 0.0f;
            if (tid == 0) s->s_kept = kept;
        }
        __syncthreads();
        if (tid >= (c + 1) * 64 && s->u.n.smult[tid] != 0.0f) {
            unsigned long long k = s->s_kept;
            while (k) {
                int t = __ffsll((long long)k) - 1;
                k &= k - 1;
                int pi = c * 64 + t;
                float4 bi = s->u.n.sbox[pi];
                float  ai = s->u.n.sarea[pi];
                float lx = fmaxf(bi.x, bj.x);
                float ly = fmaxf(bi.y, bj.y);
                float rx = fminf(bi.z, bj.z);
                float ry = fminf(bi.w, bj.w);
                float ww = fmaxf(rx - lx, 0.0f);
                float hh = fmaxf(ry - ly, 0.0f);
                if (ww > 0.0f && hh > 0.0f) {
                    float inter = ww * hh;
                    float den = ai + aj - inter + 1e-9f;
                    if (iou_gt(inter, den)) { s->u.n.smult[tid] = 0.0f; break; }
                }
            }
        }
        __syncthreads();
    }

    // ================= masked output: [ltrb(4) | kpts(10) | score(1)] * keep =================
    float* outp = out + (size_t)b * KK * 15;
    for (int e = tid; e < KK * 15; e += NT) {
        int r = e / 15;
        int c2 = e - r * 15;
        float m = s->u.n.smult[r];
        float v;
        if (c2 < 4)       v = ((const float*)&s->u.n.sbox[r])[c2];
        else if (c2 < 14) v = s->u.n.skpt[r * 10 + (c2 - 4)];
        else              v = s->u.n.sval[r];
        outp[e] = v * m;
    }
}

extern "C" void kernel_launch(void* const* d_in, const int* in_sizes, int n_in,
                              void* d_out, int out_size) {
    const float* p_loc    = (const float*)d_in[0];
    const float* p_conf   = (const float*)d_in[1];
    const float* p_landms = (const float*)d_in[2];
    const float* anchors  = (const float*)d_in[3];

    cudaFuncSetAttribute(k_fused, cudaFuncAttributeMaxDynamicSharedMemorySize, (int)sizeof(SF));
    k_fused<<<BB, NT, sizeof(SF)>>>(p_loc, p_conf, p_landms, anchors, (float*)d_out);
}